// round 15
// baseline (speedup 1.0000x reference)
#include <cuda_runtime.h>
#include <cstdint>
#include <math.h>

// Problem constants
#define BB 256      // batch
#define TT 128      // time steps
#define EMBED 256
#define HIDDEN 512
#define VOCAB 1004
#define FC_IN 2048
#define GATES 2048  // 4*HIDDEN

#define NCTA 128    // persistent recurrence grid

// ==================== helpers ====================
__device__ __forceinline__ uint32_t smem_u32(const void* p) {
    uint32_t a;
    asm("{ .reg .u64 t; cvta.to.shared.u64 t, %1; cvt.u32.u64 %0, t; }"
        : "=r"(a) : "l"(p));
    return a;
}

// Split 2 fp32 -> bf16x2 hi + bf16x2 lo (low 16 bits = first element)
__device__ __forceinline__ void split2(float x, float y, uint32_t& hi, uint32_t& lo) {
    uint32_t h;
    asm("cvt.rn.bf16x2.f32 %0, %1, %2;" : "=r"(h) : "f"(y), "f"(x));
    float fx = __uint_as_float(h << 16);
    float fy = __uint_as_float(h & 0xFFFF0000u);
    float rx = x - fx, ry = y - fy;
    uint32_t l;
    asm("cvt.rn.bf16x2.f32 %0, %1, %2;" : "=r"(l) : "f"(ry), "f"(rx));
    hi = h; lo = l;
}

__device__ __forceinline__ void ldsm4(uint32_t addr, uint32_t r[4]) {
    asm volatile("ldmatrix.sync.aligned.m8n8.x4.shared.b16 {%0,%1,%2,%3}, [%4];"
                 : "=r"(r[0]), "=r"(r[1]), "=r"(r[2]), "=r"(r[3]) : "r"(addr));
}

__device__ __forceinline__ void mma16816(float d[4], const uint32_t a[4],
                                         const uint32_t b[2]) {
    asm volatile(
        "mma.sync.aligned.m16n8k16.row.col.f32.bf16.bf16.f32 "
        "{%0,%1,%2,%3}, {%4,%5,%6,%7}, {%8,%9}, {%0,%1,%2,%3};"
        : "+f"(d[0]), "+f"(d[1]), "+f"(d[2]), "+f"(d[3])
        : "r"(a[0]), "r"(a[1]), "r"(a[2]), "r"(a[3]), "r"(b[0]), "r"(b[1]));
}

__device__ __forceinline__ void cpasync16(uint32_t dst, const void* src) {
    asm volatile("cp.async.ca.shared.global [%0], [%1], 16;"
                 :: "r"(dst), "l"(src) : "memory");
}
__device__ __forceinline__ void cpasync16z(uint32_t dst, const void* src, int sz) {
    asm volatile("cp.async.ca.shared.global [%0], [%1], 16, %2;"
                 :: "r"(dst), "l"(src), "r"(sz) : "memory");
}

// ==================== device scratch ====================
__device__ float g_base_att[BB * EMBED];
__device__ float g_base_ih[BB * GATES];
__device__ float g_bsum[GATES];
__device__ float g_gin[(size_t)BB * TT * GATES];         // 256 MB  [B,T,2048]
__device__ uint32_t g_hbuf_hi[2][BB][HIDDEN / 2];        // h packed bf16x2 (hi)
__device__ uint32_t g_hbuf_lo[2][BB][HIDDEN / 2];        // h residual (lo)
__device__ unsigned g_count;
__device__ unsigned g_epoch;

// pre-split (bf16 hi/lo) tensors: [0]=hi, [1]=lo
__device__ __align__(16) uint16_t g_images_s[2][BB * FC_IN];
__device__ __align__(16) uint16_t g_Wfc_s[2][EMBED * FC_IN];
__device__ __align__(16) uint16_t g_Watt_s[2][EMBED * (HIDDEN + EMBED)];
__device__ __align__(16) uint16_t g_Wih_s[2][GATES * 2 * EMBED];
__device__ __align__(16) uint16_t g_Wout_s[2][VOCAB * HIDDEN];
__device__ __align__(16) uint16_t g_capt_s[2][(size_t)BB * TT * HIDDEN];
__device__ __align__(16) uint16_t g_feats_s[2][BB * EMBED];
__device__ __align__(16) uint16_t g_ctx_s[2][(size_t)BB * TT * EMBED];
__device__ __align__(16) uint16_t g_hs_s[2][(size_t)BB * TT * HIDDEN];

// ==================== convert kernel: fp32 -> bf16 hi/lo ====================
__global__ void split_kernel(const float* __restrict__ X,
                             uint16_t* __restrict__ Xh,
                             uint16_t* __restrict__ Xl, int n4) {
    int i = blockIdx.x * blockDim.x + threadIdx.x;
    if (i < n4) {
        float4 v = ((const float4*)X)[i];
        uint32_t h01, l01, h23, l23;
        split2(v.x, v.y, h01, l01);
        split2(v.z, v.w, h23, l23);
        ((uint2*)Xh)[i] = make_uint2(h01, h23);
        ((uint2*)Xl)[i] = make_uint2(l01, l23);
    }
}

// ==================== pipelined bf16x3 GEMM on pre-split operands ====================
// C = A @ Bw^T with A,Bw given as bf16 hi/lo pairs (row strides in elements).
// Output: fp32 C, or split (Ch/Cl) if C == nullptr (requires N even).
// M % BM == 0, K % 32 == 0. 2-stage cp.async pipeline. 8 warps (2x4).
template <int BM, int BN>
__global__ void __launch_bounds__(256)
gemm_bf(const uint16_t* __restrict__ Ah, const uint16_t* __restrict__ Al, int lda,
        const uint16_t* __restrict__ Bh, const uint16_t* __restrict__ Bl, int ldb,
        const float* __restrict__ bias,
        const float* __restrict__ Cadd, int rowdiv,
        float* __restrict__ C, uint16_t* __restrict__ Ch, uint16_t* __restrict__ Cl,
        int M, int N, int K) {
    constexpr int WM = BM / 2;
    constexpr int WN = BN / 4;
    constexpr int MI = WM / 16;
    constexpr int NI = WN / 8;
    constexpr int LDS = 40;                  // conflict-free ldmatrix layout
    constexpr int ATILEB = BM * LDS * 2;
    constexpr int BTILEB = BN * LDS * 2;
    constexpr int STAGEB = 2 * ATILEB + 2 * BTILEB;

    extern __shared__ __align__(16) char smbf[];
    const uint32_t SB = smem_u32(smbf);

    const int tid = threadIdx.x;
    const int lane = tid & 31;
    const int wid = tid >> 5;
    const int warp_m = wid >> 2;
    const int warp_n = wid & 3;
    const int bm = blockIdx.y * BM;
    const int bn = blockIdx.x * BN;

    auto prefetch = [&](int kti) {
        const uint32_t base = SB + (kti & 1) * STAGEB;
        const int kt = kti * 32;
        constexpr int PA = BM * 4 / 256;
#pragma unroll
        for (int i = 0; i < PA; i++) {
            int p = tid + i * 256;
            int row = p >> 2, seg = p & 3;
            uint32_t d = base + (uint32_t)(row * LDS + seg * 8) * 2;
            size_t go = (size_t)(bm + row) * lda + kt + seg * 8;
            cpasync16(d, Ah + go);
            cpasync16(d + ATILEB, Al + go);
        }
        constexpr int PB = BN * 4 / 256;
#pragma unroll
        for (int i = 0; i < PB; i++) {
            int p = tid + i * 256;
            int row = p >> 2, seg = p & 3;
            int gn = bn + row;
            int sz = (gn < N) ? 16 : 0;
            int gnc = (gn < N) ? gn : (N - 1);
            uint32_t d = base + 2 * ATILEB + (uint32_t)(row * LDS + seg * 8) * 2;
            size_t go = (size_t)gnc * ldb + kt + seg * 8;
            cpasync16z(d, Bh + go, sz);
            cpasync16z(d + BTILEB, Bl + go, sz);
        }
        asm volatile("cp.async.commit_group;" ::: "memory");
    };

    float acc[MI][NI][4];
#pragma unroll
    for (int mi = 0; mi < MI; mi++)
#pragma unroll
        for (int ni = 0; ni < NI; ni++)
#pragma unroll
            for (int e = 0; e < 4; e++) acc[mi][ni][e] = 0.f;

    const int a_r = lane & 15;
    const int a_c = (lane >> 4) << 3;
    const int b_r = lane & 7;
    const int b_c = ((lane >> 3) & 1) << 3;
    const int b_m = (lane >> 4) & 1;

    const int nk = K / 32;
    prefetch(0);
    for (int kt = 0; kt < nk; kt++) {
        asm volatile("cp.async.wait_group 0;" ::: "memory");
        __syncthreads();
        if (kt + 1 < nk) prefetch(kt + 1);   // overlaps with compute below

        const uint32_t base = SB + (kt & 1) * STAGEB;
        const uint32_t sAhi = base, sAlo = base + ATILEB;
        const uint32_t sBhi = base + 2 * ATILEB, sBlo = sBhi + BTILEB;

#pragma unroll
        for (int ks = 0; ks < 2; ks++) {
            const int k0 = ks * 16;
            uint32_t ah[MI][4], al[MI][4];
#pragma unroll
            for (int mi = 0; mi < MI; mi++) {
                uint32_t off =
                    (uint32_t)((warp_m * WM + mi * 16 + a_r) * LDS + k0 + a_c) * 2;
                ldsm4(sAhi + off, ah[mi]);
                ldsm4(sAlo + off, al[mi]);
            }
            uint32_t bh[NI][2], bl[NI][2];
#pragma unroll
            for (int p = 0; p < NI / 2; p++) {
                uint32_t off =
                    (uint32_t)((warp_n * WN + (p * 2 + b_m) * 8 + b_r) * LDS +
                               k0 + b_c) * 2;
                uint32_t r4[4];
                ldsm4(sBhi + off, r4);
                bh[2 * p][0] = r4[0]; bh[2 * p][1] = r4[1];
                bh[2 * p + 1][0] = r4[2]; bh[2 * p + 1][1] = r4[3];
                ldsm4(sBlo + off, r4);
                bl[2 * p][0] = r4[0]; bl[2 * p][1] = r4[1];
                bl[2 * p + 1][0] = r4[2]; bl[2 * p + 1][1] = r4[3];
            }
#pragma unroll
            for (int mi = 0; mi < MI; mi++)
#pragma unroll
                for (int ni = 0; ni < NI; ni++) {
                    mma16816(acc[mi][ni], ah[mi], bh[ni]);
                    mma16816(acc[mi][ni], ah[mi], bl[ni]);
                    mma16816(acc[mi][ni], al[mi], bh[ni]);
                }
        }
    }

    // ---- epilogue ----
#pragma unroll
    for (int mi = 0; mi < MI; mi++) {
        int gm0 = bm + warp_m * WM + mi * 16 + (lane >> 2);
        int gm1 = gm0 + 8;
        const float* cr0 = Cadd
            ? Cadd + (size_t)(rowdiv > 1 ? gm0 / rowdiv : gm0) * N : (const float*)0;
        const float* cr1 = Cadd
            ? Cadd + (size_t)(rowdiv > 1 ? gm1 / rowdiv : gm1) * N : (const float*)0;
#pragma unroll
        for (int ni = 0; ni < NI; ni++) {
            int gn = bn + warp_n * WN + ni * 8 + (lane & 3) * 2;
            if (gn >= N) continue;
            float b0 = bias ? bias[gn] : 0.f;
            float b1 = (bias && gn + 1 < N) ? bias[gn + 1] : 0.f;
            float2 v0, v1;
            v0.x = acc[mi][ni][0] + b0 + (cr0 ? cr0[gn] : 0.f);
            v1.x = acc[mi][ni][2] + b0 + (cr1 ? cr1[gn] : 0.f);
            v0.y = acc[mi][ni][1] + b1;
            v1.y = acc[mi][ni][3] + b1;
            if (gn + 1 < N) {
                if (cr0) v0.y += cr0[gn + 1];
                if (cr1) v1.y += cr1[gn + 1];
            }
            if (C) {
                if (gn + 1 < N) {
                    *(float2*)(C + (size_t)gm0 * N + gn) = v0;
                    *(float2*)(C + (size_t)gm1 * N + gn) = v1;
                } else {
                    C[(size_t)gm0 * N + gn] = v0.x;
                    C[(size_t)gm1 * N + gn] = v1.x;
                }
            } else {
                // split output (N even here)
                uint32_t h0, l0, h1, l1;
                split2(v0.x, v0.y, h0, l0);
                split2(v1.x, v1.y, h1, l1);
                *(uint32_t*)(Ch + (size_t)gm0 * N + gn) = h0;
                *(uint32_t*)(Cl + (size_t)gm0 * N + gn) = l0;
                *(uint32_t*)(Ch + (size_t)gm1 * N + gn) = h1;
                *(uint32_t*)(Cl + (size_t)gm1 * N + gn) = l1;
            }
        }
    }
}

// ==================== init kernel: bias sum + barrier reset ====================
__global__ void init_kernel(const float* __restrict__ b_ih,
                            const float* __restrict__ b_hh,
                            float* __restrict__ bsum) {
    int n = blockIdx.x * blockDim.x + threadIdx.x;
    if (n < GATES) bsum[n] = b_ih[n] + b_hh[n];
    if (n == 0) { g_count = 0u; g_epoch = 0u; }
}

__device__ __forceinline__ float sigmoidf_(float x) {
    return 1.f / (1.f + expf(-x));
}

// ==================== persistent tensorized recurrence ====================
// SMEM layout (bytes):
//  WS_HI 0       : 32 x 520 bf16  (33280)
//  WS_LO 33280   : 32 x 520 bf16  (33280)
//  HS    66560   : 2 x (hi 128x72 bf16 + lo) = 73728
//  GS    140288  : 128 x 33 fp32  (16896)
//  CS    157184  : 128 x 8  fp32  (4096)
//  GB    161280  : 128 x 36 fp32  (18432)   gin prefetch tile
#define LDSW 520
#define LDH  72
#define R_WS_LO 33280
#define R_HS    66560
#define R_HBUF  36864
#define R_HLO   18432
#define R_GS    140288
#define R_CS    157184
#define R_GB    161280
#define R_TOTAL 179712

__global__ void __launch_bounds__(256, 1)
lstm_persistent(const float* __restrict__ W_hh,   // [2048,512]
                const float* __restrict__ gin)    // [B,T,2048]
{
    extern __shared__ __align__(16) char sm[];
    const uint32_t SB = smem_u32(sm);
    float* Gs = (float*)(sm + R_GS);
    float* Cs = (float*)(sm + R_CS);
    const float* Gb = (const float*)(sm + R_GB);

    const int tid = threadIdx.x;
    const int lane = tid & 31;
    const int wid = tid >> 5;
    const int warp_m = wid >> 1;    // 0..3
    const int warp_n = wid & 1;     // 0..1
    const int bid = blockIdx.x;
    const int bbase = (bid & 1) * 128;
    const int jbase = (bid >> 1) * 8;

    // ---- cache W_hh slice in SMEM as bf16 hi+lo (once) ----
#pragma unroll
    for (int i = 0; i < 16; i++) {
        int idx = tid + i * 256;
        int c = idx >> 7;
        int q = idx & 127;
        int gcol = (c >> 3) * 512 + jbase + (c & 7);
        float4 v = *(const float4*)(W_hh + (size_t)gcol * HIDDEN + q * 4);
        uint32_t h01, l01, h23, l23;
        split2(v.x, v.y, h01, l01);
        split2(v.z, v.w, h23, l23);
        uint32_t off = (uint32_t)(c * LDSW + q * 4) * 2;
        asm volatile("st.shared.v2.b32 [%0], {%1, %2};"
                     :: "r"(SB + off), "r"(h01), "r"(h23) : "memory");
        asm volatile("st.shared.v2.b32 [%0], {%1, %2};"
                     :: "r"(SB + R_WS_LO + off), "r"(l01), "r"(l23) : "memory");
    }
    __syncthreads();

    const int a_r = lane & 15;
    const int a_c = (lane >> 4) << 3;
    const int b_r = lane & 7;
    const int b_c = ((lane >> 3) & 1) << 3;
    const int b_m = (lane >> 4) & 1;
    const uint32_t b_row_off = (uint32_t)((warp_n * 16 + b_m * 8 + b_r) * LDSW) * 2;

    unsigned epoch = 0;

    for (int t = 0; t < TT; t++) {
        // ---- prefetch gin tile [128 x 32] into GB (group committed FIRST) ----
#pragma unroll
        for (int i = 0; i < 4; i++) {
            int p = tid + i * 256;      // 0..1023 over [128 rows][8 chunks]
            int row = p >> 3;
            int c4 = p & 7;
            int col = (c4 >> 1) * 8 + (c4 & 1) * 4;  // gate*8 + jj
            uint32_t d = SB + R_GB + (uint32_t)(row * 36 + col) * 4;
            const float* s = gin + ((size_t)(bbase + row) * TT + t) * GATES +
                             (c4 >> 1) * 512 + jbase + (c4 & 1) * 4;
            cpasync16(d, s);
        }
        asm volatile("cp.async.commit_group;" ::: "memory");

        float acc[2][2][4];
#pragma unroll
        for (int mi = 0; mi < 2; mi++)
#pragma unroll
            for (int ni = 0; ni < 2; ni++)
#pragma unroll
                for (int e = 0; e < 4; e++) acc[mi][ni][e] = 0.f;

        if (t > 0) {
            const int hb = (t - 1) & 1;

            auto prefetch = [&](int kc, int buf) {
                const uint32_t dbase = SB + R_HS + buf * R_HBUF;
                const int kt2 = kc * 32;
#pragma unroll
                for (int i = 0; i < 4; i++) {
                    int j = tid + i * 256;
                    int row = j >> 3;
                    int seg = j & 7;
                    uint32_t d = dbase + (uint32_t)(row * LDH + seg * 8) * 2;
                    cpasync16(d, &g_hbuf_hi[hb][bbase + row][kt2 + seg * 4]);
                    cpasync16(d + R_HLO, &g_hbuf_lo[hb][bbase + row][kt2 + seg * 4]);
                }
                asm volatile("cp.async.commit_group;" ::: "memory");
            };

            prefetch(0, 0);
            prefetch(1, 1);

            for (int kc = 0; kc < 8; kc++) {
                if (kc == 7) {
                    asm volatile("cp.async.wait_group 0;" ::: "memory");
                } else {
                    asm volatile("cp.async.wait_group 1;" ::: "memory");
                }
                __syncthreads();

                const uint32_t hsb = SB + R_HS + (kc & 1) * R_HBUF;
                const int ktg = kc * 64;
#pragma unroll
                for (int ks = 0; ks < 4; ks++) {
                    const int k0 = ks * 16;
                    uint32_t ah[2][4], al[2][4];
#pragma unroll
                    for (int mi = 0; mi < 2; mi++) {
                        uint32_t off = hsb +
                            (uint32_t)((warp_m * 32 + mi * 16 + a_r) * LDH +
                                       k0 + a_c) * 2;
                        ldsm4(off, ah[mi]);
                        ldsm4(off + R_HLO, al[mi]);
                    }
                    uint32_t bh[2][2], bl[2][2];
                    {
                        uint32_t off = SB + b_row_off +
                                       (uint32_t)(ktg + k0 + b_c) * 2;
                        uint32_t r4[4];
                        ldsm4(off, r4);
                        bh[0][0] = r4[0]; bh[0][1] = r4[1];
                        bh[1][0] = r4[2]; bh[1][1] = r4[3];
                        ldsm4(off + R_WS_LO, r4);
                        bl[0][0] = r4[0]; bl[0][1] = r4[1];
                        bl[1][0] = r4[2]; bl[1][1] = r4[3];
                    }
#pragma unroll
                    for (int mi = 0; mi < 2; mi++)
#pragma unroll
                        for (int ni = 0; ni < 2; ni++) {
                            mma16816(acc[mi][ni], ah[mi], bh[ni]);
                            mma16816(acc[mi][ni], ah[mi], bl[ni]);
                            mma16816(acc[mi][ni], al[mi], bh[ni]);
                        }
                }
                __syncthreads();
                if (kc < 6) prefetch(kc + 2, kc & 1);
            }
            // after kc==7: wait_group 0 done (gin tile included), sync passed
        } else {
            asm volatile("cp.async.wait_group 0;" ::: "memory");
            __syncthreads();
        }

        // ---- frags + gin(smem) -> Gs ----
#pragma unroll
        for (int mi = 0; mi < 2; mi++) {
            int r0 = warp_m * 32 + mi * 16 + (lane >> 2);
            int r1 = r0 + 8;
#pragma unroll
            for (int ni = 0; ni < 2; ni++) {
                int c = warp_n * 16 + ni * 8 + (lane & 3) * 2;  // == gate*8+jj
                float2 g0 = *(const float2*)(Gb + r0 * 36 + c);
                float2 g1 = *(const float2*)(Gb + r1 * 36 + c);
                Gs[r0 * 33 + c]     = acc[mi][ni][0] + g0.x;
                Gs[r0 * 33 + c + 1] = acc[mi][ni][1] + g0.y;
                Gs[r1 * 33 + c]     = acc[mi][ni][2] + g1.x;
                Gs[r1 * 33 + c + 1] = acc[mi][ni][3] + g1.y;
            }
        }
        __syncthreads();

        // ---- LSTM cell ----
        {
            int q0 = tid * 4;
            int bl = q0 >> 3;
            int jj0 = q0 & 7;
            float hhv[4];
#pragma unroll
            for (int s = 0; s < 4; s++) {
                int jj = jj0 + s;
                float gi = Gs[bl * 33 + jj];
                float gf = Gs[bl * 33 + 8 + jj];
                float gg = Gs[bl * 33 + 16 + jj];
                float go = Gs[bl * 33 + 24 + jj];
                float cprev = (t == 0) ? 0.f : Cs[bl * 8 + jj];
                float cc = sigmoidf_(gf) * cprev + sigmoidf_(gi) * tanhf(gg);
                hhv[s] = sigmoidf_(go) * tanhf(cc);
                Cs[bl * 8 + jj] = cc;
            }
            uint32_t h01, l01, h23, l23;
            split2(hhv[0], hhv[1], h01, l01);
            split2(hhv[2], hhv[3], h23, l23);
            // split hs output (consumed by out-GEMM)
            size_t ho = ((size_t)(bbase + bl) * TT + t) * HIDDEN + jbase + jj0;
            *(uint2*)&g_hs_s[0][ho] = make_uint2(h01, h23);
            *(uint2*)&g_hs_s[1][ho] = make_uint2(l01, l23);
            // packed h for next step
            int pc = (jbase + jj0) >> 1;
            g_hbuf_hi[t & 1][bbase + bl][pc]     = h01;
            g_hbuf_hi[t & 1][bbase + bl][pc + 1] = h23;
            g_hbuf_lo[t & 1][bbase + bl][pc]     = l01;
            g_hbuf_lo[t & 1][bbase + bl][pc + 1] = l23;
        }

        // ---- grid barrier (monotonic) ----
        if (t < TT - 1) {
            epoch++;
            __syncthreads();
            if (tid == 0) {
                __threadfence();
                unsigned arrived = atomicAdd(&g_count, 1u);
                if (arrived == epoch * NCTA - 1u) {
                    atomicExch(&g_epoch, epoch);
                } else {
                    volatile unsigned* ep = &g_epoch;
                    while (*ep < epoch) { __nanosleep(64); }
                }
                __threadfence();
            }
            __syncthreads();
        }
    }
}

// ==================== launch ====================
extern "C" void kernel_launch(void* const* d_in, const int* in_sizes, int n_in,
                              void* d_out, int out_size) {
    const float* images   = (const float*)d_in[0];   // [256, 2048]
    const float* captions = (const float*)d_in[1];   // [256, 128, 512]
    const float* W_fc     = (const float*)d_in[2];   // [256, 2048]
    const float* b_fc     = (const float*)d_in[3];   // [256]
    const float* W_att    = (const float*)d_in[4];   // [256, 768]
    const float* b_att    = (const float*)d_in[5];   // [256]
    const float* W_ih     = (const float*)d_in[6];   // [2048, 512]
    const float* b_ih     = (const float*)d_in[7];   // [2048]
    const float* W_hh     = (const float*)d_in[8];   // [2048, 512]
    const float* b_hh     = (const float*)d_in[9];   // [2048]
    const float* W_out    = (const float*)d_in[10];  // [1004, 512]
    const float* b_out    = (const float*)d_in[11];  // [1004]
    float* out = (float*)d_out;                      // [256, 128, 1004]

    static bool inited = false;
    static float *p_batt, *p_bih, *p_bsum, *p_gin;
    static uint16_t *im_h, *im_l, *wfc_h, *wfc_l, *wat_h, *wat_l,
                    *wih_h, *wih_l, *wo_h, *wo_l, *cap_h, *cap_l,
                    *fe_h, *fe_l, *cx_h, *cx_l, *hsh, *hsl;
    if (!inited) {
        inited = true;
        cudaGetSymbolAddress((void**)&p_batt, g_base_att);
        cudaGetSymbolAddress((void**)&p_bih, g_base_ih);
        cudaGetSymbolAddress((void**)&p_bsum, g_bsum);
        cudaGetSymbolAddress((void**)&p_gin, g_gin);
        uint16_t* t2;
        cudaGetSymbolAddress((void**)&t2, g_images_s); im_h = t2; im_l = t2 + BB * FC_IN;
        cudaGetSymbolAddress((void**)&t2, g_Wfc_s);   wfc_h = t2; wfc_l = t2 + EMBED * FC_IN;
        cudaGetSymbolAddress((void**)&t2, g_Watt_s);  wat_h = t2; wat_l = t2 + EMBED * (HIDDEN + EMBED);
        cudaGetSymbolAddress((void**)&t2, g_Wih_s);   wih_h = t2; wih_l = t2 + GATES * 2 * EMBED;
        cudaGetSymbolAddress((void**)&t2, g_Wout_s);  wo_h = t2;  wo_l = t2 + VOCAB * HIDDEN;
        cudaGetSymbolAddress((void**)&t2, g_capt_s);  cap_h = t2; cap_l = t2 + (size_t)BB * TT * HIDDEN;
        cudaGetSymbolAddress((void**)&t2, g_feats_s); fe_h = t2;  fe_l = t2 + BB * EMBED;
        cudaGetSymbolAddress((void**)&t2, g_ctx_s);   cx_h = t2;  cx_l = t2 + (size_t)BB * TT * EMBED;
        cudaGetSymbolAddress((void**)&t2, g_hs_s);    hsh = t2;   hsl = t2 + (size_t)BB * TT * HIDDEN;

        cudaFuncSetAttribute(lstm_persistent,
                             cudaFuncAttributeMaxDynamicSharedMemorySize, R_TOTAL);
        cudaFuncSetAttribute(gemm_bf<128, 128>,
                             cudaFuncAttributeMaxDynamicSharedMemorySize, 81920);
        cudaFuncSetAttribute(gemm_bf<64, 64>,
                             cudaFuncAttributeMaxDynamicSharedMemorySize, 40960);
    }

    auto split = [&](const float* X, uint16_t* Xh, uint16_t* Xl, size_t n) {
        int n4 = (int)(n / 4);
        split_kernel<<<(n4 + 255) / 256, 256>>>(X, Xh, Xl, n4);
    };
    auto tc = [&](const uint16_t* Ah, const uint16_t* Al, int lda,
                  const uint16_t* Bh, const uint16_t* Bl, int ldb,
                  const float* bias, const float* Cadd, int rowdiv,
                  float* C, uint16_t* Ch, uint16_t* Cl, int M, int N, int K) {
        dim3 grid((N + 127) / 128, M / 128);
        gemm_bf<128, 128><<<grid, 256, 81920>>>(Ah, Al, lda, Bh, Bl, ldb,
                                                bias, Cadd, rowdiv,
                                                C, Ch, Cl, M, N, K);
    };
    auto tcs = [&](const uint16_t* Ah, const uint16_t* Al, int lda,
                   const uint16_t* Bh, const uint16_t* Bl, int ldb,
                   const float* bias, const float* Cadd, int rowdiv,
                   float* C, uint16_t* Ch, uint16_t* Cl, int M, int N, int K) {
        dim3 grid((N + 63) / 64, M / 64);
        gemm_bf<64, 64><<<grid, 256, 40960>>>(Ah, Al, lda, Bh, Bl, ldb,
                                              bias, Cadd, rowdiv,
                                              C, Ch, Cl, M, N, K);
    };

    // init + convert inputs/weights to split bf16
    init_kernel<<<(GATES + 255) / 256, 256>>>(b_ih, b_hh, p_bsum);
    split(images, im_h, im_l, (size_t)BB * FC_IN);
    split(W_fc, wfc_h, wfc_l, (size_t)EMBED * FC_IN);
    split(W_att, wat_h, wat_l, (size_t)EMBED * (HIDDEN + EMBED));
    split(W_ih, wih_h, wih_l, (size_t)GATES * 2 * EMBED);
    split(W_out, wo_h, wo_l, (size_t)VOCAB * HIDDEN);
    split(captions, cap_h, cap_l, (size_t)BB * TT * HIDDEN);

    // feats(split) = images @ W_fc^T + b_fc            [256,256] K=2048
    tcs(im_h, im_l, FC_IN, wfc_h, wfc_l, FC_IN, b_fc, nullptr, 0,
        nullptr, fe_h, fe_l, BB, EMBED, FC_IN);

    // base_att = feats @ W_att[:, :256]^T + b_att      [256,256] K=256
    tcs(fe_h, fe_l, EMBED, wat_h, wat_l, HIDDEN + EMBED, b_att, nullptr, 0,
        p_batt, nullptr, nullptr, BB, EMBED, EMBED);

    // base_ih = feats @ W_ih[:, :256]^T + (b_ih+b_hh)  [256,2048] K=256
    tcs(fe_h, fe_l, EMBED, wih_h, wih_l, 2 * EMBED, p_bsum, nullptr, 0,
        p_bih, nullptr, nullptr, BB, GATES, EMBED);

    // ctx(split) = captions @ W_att[:, 256:]^T + base_att[b]   [32768,256] K=512
    tc(cap_h, cap_l, HIDDEN, wat_h + EMBED, wat_l + EMBED, HIDDEN + EMBED,
       nullptr, p_batt, TT, nullptr, cx_h, cx_l, BB * TT, EMBED, HIDDEN);

    // gin = ctx @ W_ih[:, 256:]^T + base_ih[b]         [32768,2048] K=256
    tc(cx_h, cx_l, EMBED, wih_h + EMBED, wih_l + EMBED, 2 * EMBED,
       nullptr, p_bih, TT, p_gin, nullptr, nullptr, BB * TT, GATES, EMBED);

    // full recurrence (writes split hs + hbuf)
    lstm_persistent<<<NCTA, 256, R_TOTAL>>>(W_hh, p_gin);

    // out = hs @ W_out^T + b_out                       [32768,1004] K=512
    tc(hsh, hsl, HIDDEN, wo_h, wo_l, HIDDEN, b_out, nullptr, 0,
       out, nullptr, nullptr, BB * TT, VOCAB, HIDDEN);
}

// round 16
// speedup vs baseline: 1.0056x; 1.0056x over previous
#include <cuda_runtime.h>
#include <cstdint>
#include <math.h>

// Problem constants
#define BB 256      // batch
#define TT 128      // time steps
#define EMBED 256
#define HIDDEN 512
#define VOCAB 1004
#define FC_IN 2048
#define GATES 2048  // 4*HIDDEN

#define NCTA 128    // persistent recurrence grid

// ==================== helpers ====================
__device__ __forceinline__ uint32_t smem_u32(const void* p) {
    uint32_t a;
    asm("{ .reg .u64 t; cvta.to.shared.u64 t, %1; cvt.u32.u64 %0, t; }"
        : "=r"(a) : "l"(p));
    return a;
}

// Split 2 fp32 -> bf16x2 hi + bf16x2 lo (low 16 bits = first element)
__device__ __forceinline__ void split2(float x, float y, uint32_t& hi, uint32_t& lo) {
    uint32_t h;
    asm("cvt.rn.bf16x2.f32 %0, %1, %2;" : "=r"(h) : "f"(y), "f"(x));
    float fx = __uint_as_float(h << 16);
    float fy = __uint_as_float(h & 0xFFFF0000u);
    float rx = x - fx, ry = y - fy;
    uint32_t l;
    asm("cvt.rn.bf16x2.f32 %0, %1, %2;" : "=r"(l) : "f"(ry), "f"(rx));
    hi = h; lo = l;
}

__device__ __forceinline__ void ldsm4(uint32_t addr, uint32_t r[4]) {
    asm volatile("ldmatrix.sync.aligned.m8n8.x4.shared.b16 {%0,%1,%2,%3}, [%4];"
                 : "=r"(r[0]), "=r"(r[1]), "=r"(r[2]), "=r"(r[3]) : "r"(addr));
}

__device__ __forceinline__ void mma16816(float d[4], const uint32_t a[4],
                                         const uint32_t b[2]) {
    asm volatile(
        "mma.sync.aligned.m16n8k16.row.col.f32.bf16.bf16.f32 "
        "{%0,%1,%2,%3}, {%4,%5,%6,%7}, {%8,%9}, {%0,%1,%2,%3};"
        : "+f"(d[0]), "+f"(d[1]), "+f"(d[2]), "+f"(d[3])
        : "r"(a[0]), "r"(a[1]), "r"(a[2]), "r"(a[3]), "r"(b[0]), "r"(b[1]));
}

__device__ __forceinline__ void cpasync16(uint32_t dst, const void* src) {
    asm volatile("cp.async.ca.shared.global [%0], [%1], 16;"
                 :: "r"(dst), "l"(src) : "memory");
}
__device__ __forceinline__ void cpasync16z(uint32_t dst, const void* src, int sz) {
    asm volatile("cp.async.ca.shared.global [%0], [%1], 16, %2;"
                 :: "r"(dst), "l"(src), "r"(sz) : "memory");
}

// ==================== device scratch ====================
__device__ float g_base_att[BB * EMBED];
__device__ float g_base_ih[BB * GATES];
__device__ float g_bsum[GATES];
__device__ float g_gin[(size_t)BB * TT * GATES];         // 256 MB  [B,T,2048]
__device__ uint32_t g_hbuf_hi[2][BB][HIDDEN / 2];        // h packed bf16x2 (hi)
__device__ uint32_t g_hbuf_lo[2][BB][HIDDEN / 2];        // h residual (lo)
__device__ unsigned g_count;
__device__ unsigned g_epoch;

// pre-split (bf16 hi/lo) tensors: [0]=hi, [1]=lo
__device__ __align__(16) uint16_t g_images_s[2][BB * FC_IN];
__device__ __align__(16) uint16_t g_Wfc_s[2][EMBED * FC_IN];
__device__ __align__(16) uint16_t g_Watt_s[2][EMBED * (HIDDEN + EMBED)];
__device__ __align__(16) uint16_t g_Wih_s[2][GATES * 2 * EMBED];
__device__ __align__(16) uint16_t g_Wout_s[2][VOCAB * HIDDEN];
__device__ __align__(16) uint16_t g_capt_s[2][(size_t)BB * TT * HIDDEN];
__device__ __align__(16) uint16_t g_feats_s[2][BB * EMBED];
__device__ __align__(16) uint16_t g_ctx_s[2][(size_t)BB * TT * EMBED];
__device__ __align__(16) uint16_t g_hs_s[2][(size_t)BB * TT * HIDDEN];

// ==================== convert kernel: fp32 -> bf16 hi/lo ====================
__global__ void split_kernel(const float* __restrict__ X,
                             uint16_t* __restrict__ Xh,
                             uint16_t* __restrict__ Xl, int n4) {
    int i = blockIdx.x * blockDim.x + threadIdx.x;
    if (i < n4) {
        float4 v = ((const float4*)X)[i];
        uint32_t h01, l01, h23, l23;
        split2(v.x, v.y, h01, l01);
        split2(v.z, v.w, h23, l23);
        ((uint2*)Xh)[i] = make_uint2(h01, h23);
        ((uint2*)Xl)[i] = make_uint2(l01, l23);
    }
}

// ==================== pipelined bf16x3 GEMM on pre-split operands ====================
// C = A @ Bw^T with A,Bw given as bf16 hi/lo pairs (row strides in elements).
// Output: fp32 C, or split (Ch/Cl) if C == nullptr (requires N even).
// M % BM == 0, K % 32 == 0. 2-stage cp.async pipeline. 8 warps (2x4).
template <int BM, int BN>
__global__ void __launch_bounds__(256)
gemm_bf(const uint16_t* __restrict__ Ah, const uint16_t* __restrict__ Al, int lda,
        const uint16_t* __restrict__ Bh, const uint16_t* __restrict__ Bl, int ldb,
        const float* __restrict__ bias,
        const float* __restrict__ Cadd, int rowdiv,
        float* __restrict__ C, uint16_t* __restrict__ Ch, uint16_t* __restrict__ Cl,
        int M, int N, int K) {
    constexpr int WM = BM / 2;
    constexpr int WN = BN / 4;
    constexpr int MI = WM / 16;
    constexpr int NI = WN / 8;
    constexpr int LDS = 40;                  // conflict-free ldmatrix layout
    constexpr int ATILEB = BM * LDS * 2;
    constexpr int BTILEB = BN * LDS * 2;
    constexpr int STAGEB = 2 * ATILEB + 2 * BTILEB;

    extern __shared__ __align__(16) char smbf[];
    const uint32_t SB = smem_u32(smbf);

    const int tid = threadIdx.x;
    const int lane = tid & 31;
    const int wid = tid >> 5;
    const int warp_m = wid >> 2;
    const int warp_n = wid & 3;
    const int bm = blockIdx.y * BM;
    const int bn = blockIdx.x * BN;

    auto prefetch = [&](int kti) {
        const uint32_t base = SB + (kti & 1) * STAGEB;
        const int kt = kti * 32;
        constexpr int PA = BM * 4 / 256;
#pragma unroll
        for (int i = 0; i < PA; i++) {
            int p = tid + i * 256;
            int row = p >> 2, seg = p & 3;
            uint32_t d = base + (uint32_t)(row * LDS + seg * 8) * 2;
            size_t go = (size_t)(bm + row) * lda + kt + seg * 8;
            cpasync16(d, Ah + go);
            cpasync16(d + ATILEB, Al + go);
        }
        constexpr int PB = BN * 4 / 256;
#pragma unroll
        for (int i = 0; i < PB; i++) {
            int p = tid + i * 256;
            int row = p >> 2, seg = p & 3;
            int gn = bn + row;
            int sz = (gn < N) ? 16 : 0;
            int gnc = (gn < N) ? gn : (N - 1);
            uint32_t d = base + 2 * ATILEB + (uint32_t)(row * LDS + seg * 8) * 2;
            size_t go = (size_t)gnc * ldb + kt + seg * 8;
            cpasync16z(d, Bh + go, sz);
            cpasync16z(d + BTILEB, Bl + go, sz);
        }
        asm volatile("cp.async.commit_group;" ::: "memory");
    };

    float acc[MI][NI][4];
#pragma unroll
    for (int mi = 0; mi < MI; mi++)
#pragma unroll
        for (int ni = 0; ni < NI; ni++)
#pragma unroll
            for (int e = 0; e < 4; e++) acc[mi][ni][e] = 0.f;

    const int a_r = lane & 15;
    const int a_c = (lane >> 4) << 3;
    const int b_r = lane & 7;
    const int b_c = ((lane >> 3) & 1) << 3;
    const int b_m = (lane >> 4) & 1;

    const int nk = K / 32;
    prefetch(0);
    for (int kt = 0; kt < nk; kt++) {
        asm volatile("cp.async.wait_group 0;" ::: "memory");
        __syncthreads();
        if (kt + 1 < nk) prefetch(kt + 1);   // overlaps with compute below

        const uint32_t base = SB + (kt & 1) * STAGEB;
        const uint32_t sAhi = base, sAlo = base + ATILEB;
        const uint32_t sBhi = base + 2 * ATILEB, sBlo = sBhi + BTILEB;

#pragma unroll
        for (int ks = 0; ks < 2; ks++) {
            const int k0 = ks * 16;
            uint32_t ah[MI][4], al[MI][4];
#pragma unroll
            for (int mi = 0; mi < MI; mi++) {
                uint32_t off =
                    (uint32_t)((warp_m * WM + mi * 16 + a_r) * LDS + k0 + a_c) * 2;
                ldsm4(sAhi + off, ah[mi]);
                ldsm4(sAlo + off, al[mi]);
            }
            uint32_t bh[NI][2], bl[NI][2];
#pragma unroll
            for (int p = 0; p < NI / 2; p++) {
                uint32_t off =
                    (uint32_t)((warp_n * WN + (p * 2 + b_m) * 8 + b_r) * LDS +
                               k0 + b_c) * 2;
                uint32_t r4[4];
                ldsm4(sBhi + off, r4);
                bh[2 * p][0] = r4[0]; bh[2 * p][1] = r4[1];
                bh[2 * p + 1][0] = r4[2]; bh[2 * p + 1][1] = r4[3];
                ldsm4(sBlo + off, r4);
                bl[2 * p][0] = r4[0]; bl[2 * p][1] = r4[1];
                bl[2 * p + 1][0] = r4[2]; bl[2 * p + 1][1] = r4[3];
            }
#pragma unroll
            for (int mi = 0; mi < MI; mi++)
#pragma unroll
                for (int ni = 0; ni < NI; ni++) {
                    mma16816(acc[mi][ni], ah[mi], bh[ni]);
                    mma16816(acc[mi][ni], ah[mi], bl[ni]);
                    mma16816(acc[mi][ni], al[mi], bh[ni]);
                }
        }
    }

    // ---- epilogue ----
#pragma unroll
    for (int mi = 0; mi < MI; mi++) {
        int gm0 = bm + warp_m * WM + mi * 16 + (lane >> 2);
        int gm1 = gm0 + 8;
        const float* cr0 = Cadd
            ? Cadd + (size_t)(rowdiv > 1 ? gm0 / rowdiv : gm0) * N : (const float*)0;
        const float* cr1 = Cadd
            ? Cadd + (size_t)(rowdiv > 1 ? gm1 / rowdiv : gm1) * N : (const float*)0;
#pragma unroll
        for (int ni = 0; ni < NI; ni++) {
            int gn = bn + warp_n * WN + ni * 8 + (lane & 3) * 2;
            if (gn >= N) continue;
            float b0 = bias ? bias[gn] : 0.f;
            float b1 = (bias && gn + 1 < N) ? bias[gn + 1] : 0.f;
            float2 v0, v1;
            v0.x = acc[mi][ni][0] + b0 + (cr0 ? cr0[gn] : 0.f);
            v1.x = acc[mi][ni][2] + b0 + (cr1 ? cr1[gn] : 0.f);
            v0.y = acc[mi][ni][1] + b1;
            v1.y = acc[mi][ni][3] + b1;
            if (gn + 1 < N) {
                if (cr0) v0.y += cr0[gn + 1];
                if (cr1) v1.y += cr1[gn + 1];
            }
            if (C) {
                if (gn + 1 < N) {
                    *(float2*)(C + (size_t)gm0 * N + gn) = v0;
                    *(float2*)(C + (size_t)gm1 * N + gn) = v1;
                } else {
                    C[(size_t)gm0 * N + gn] = v0.x;
                    C[(size_t)gm1 * N + gn] = v1.x;
                }
            } else {
                // split output (N even here)
                uint32_t h0, l0, h1, l1;
                split2(v0.x, v0.y, h0, l0);
                split2(v1.x, v1.y, h1, l1);
                *(uint32_t*)(Ch + (size_t)gm0 * N + gn) = h0;
                *(uint32_t*)(Cl + (size_t)gm0 * N + gn) = l0;
                *(uint32_t*)(Ch + (size_t)gm1 * N + gn) = h1;
                *(uint32_t*)(Cl + (size_t)gm1 * N + gn) = l1;
            }
        }
    }
}

// ==================== init kernel: bias sum + barrier reset ====================
__global__ void init_kernel(const float* __restrict__ b_ih,
                            const float* __restrict__ b_hh,
                            float* __restrict__ bsum) {
    int n = blockIdx.x * blockDim.x + threadIdx.x;
    if (n < GATES) bsum[n] = b_ih[n] + b_hh[n];
    if (n == 0) { g_count = 0u; g_epoch = 0u; }
}

__device__ __forceinline__ float sigmoidf_(float x) {
    return 1.f / (1.f + expf(-x));
}

// ==================== persistent tensorized recurrence ====================
// SMEM layout (bytes):
//  WS_HI 0       : 32 x 520 bf16  (33280)
//  WS_LO 33280   : 32 x 520 bf16  (33280)
//  HS    66560   : 2 x (hi 128x72 bf16 + lo) = 73728
//  GS    140288  : 128 x 33 fp32  (16896)
//  CS    157184  : 128 x 8  fp32  (4096)
//  GB    161280  : 128 x 36 fp32  (18432)   gin prefetch tile
#define LDSW 520
#define LDH  72
#define R_WS_LO 33280
#define R_HS    66560
#define R_HBUF  36864
#define R_HLO   18432
#define R_GS    140288
#define R_CS    157184
#define R_GB    161280
#define R_TOTAL 179712

__global__ void __launch_bounds__(256, 1)
lstm_persistent(const float* __restrict__ W_hh,   // [2048,512]
                const float* __restrict__ gin)    // [B,T,2048]
{
    extern __shared__ __align__(16) char sm[];
    const uint32_t SB = smem_u32(sm);
    float* Gs = (float*)(sm + R_GS);
    float* Cs = (float*)(sm + R_CS);
    const float* Gb = (const float*)(sm + R_GB);

    const int tid = threadIdx.x;
    const int lane = tid & 31;
    const int wid = tid >> 5;
    const int warp_m = wid >> 1;    // 0..3
    const int warp_n = wid & 1;     // 0..1
    const int bid = blockIdx.x;
    const int bbase = (bid & 1) * 128;
    const int jbase = (bid >> 1) * 8;

    // ---- cache W_hh slice in SMEM as bf16 hi+lo (once) ----
#pragma unroll
    for (int i = 0; i < 16; i++) {
        int idx = tid + i * 256;
        int c = idx >> 7;
        int q = idx & 127;
        int gcol = (c >> 3) * 512 + jbase + (c & 7);
        float4 v = *(const float4*)(W_hh + (size_t)gcol * HIDDEN + q * 4);
        uint32_t h01, l01, h23, l23;
        split2(v.x, v.y, h01, l01);
        split2(v.z, v.w, h23, l23);
        uint32_t off = (uint32_t)(c * LDSW + q * 4) * 2;
        asm volatile("st.shared.v2.b32 [%0], {%1, %2};"
                     :: "r"(SB + off), "r"(h01), "r"(h23) : "memory");
        asm volatile("st.shared.v2.b32 [%0], {%1, %2};"
                     :: "r"(SB + R_WS_LO + off), "r"(l01), "r"(l23) : "memory");
    }
    __syncthreads();

    const int a_r = lane & 15;
    const int a_c = (lane >> 4) << 3;
    const int b_r = lane & 7;
    const int b_c = ((lane >> 3) & 1) << 3;
    const int b_m = (lane >> 4) & 1;
    const uint32_t b_row_off = (uint32_t)((warp_n * 16 + b_m * 8 + b_r) * LDSW) * 2;

    unsigned epoch = 0;

    for (int t = 0; t < TT; t++) {
        // ---- prefetch gin tile [128 x 32] into GB (group committed FIRST) ----
#pragma unroll
        for (int i = 0; i < 4; i++) {
            int p = tid + i * 256;      // 0..1023 over [128 rows][8 chunks]
            int row = p >> 3;
            int c4 = p & 7;
            int col = (c4 >> 1) * 8 + (c4 & 1) * 4;  // gate*8 + jj
            uint32_t d = SB + R_GB + (uint32_t)(row * 36 + col) * 4;
            const float* s = gin + ((size_t)(bbase + row) * TT + t) * GATES +
                             (c4 >> 1) * 512 + jbase + (c4 & 1) * 4;
            cpasync16(d, s);
        }
        asm volatile("cp.async.commit_group;" ::: "memory");

        float acc[2][2][4];
#pragma unroll
        for (int mi = 0; mi < 2; mi++)
#pragma unroll
            for (int ni = 0; ni < 2; ni++)
#pragma unroll
                for (int e = 0; e < 4; e++) acc[mi][ni][e] = 0.f;

        if (t > 0) {
            const int hb = (t - 1) & 1;

            auto prefetch = [&](int kc, int buf) {
                const uint32_t dbase = SB + R_HS + buf * R_HBUF;
                const int kt2 = kc * 32;
#pragma unroll
                for (int i = 0; i < 4; i++) {
                    int j = tid + i * 256;
                    int row = j >> 3;
                    int seg = j & 7;
                    uint32_t d = dbase + (uint32_t)(row * LDH + seg * 8) * 2;
                    cpasync16(d, &g_hbuf_hi[hb][bbase + row][kt2 + seg * 4]);
                    cpasync16(d + R_HLO, &g_hbuf_lo[hb][bbase + row][kt2 + seg * 4]);
                }
                asm volatile("cp.async.commit_group;" ::: "memory");
            };

            prefetch(0, 0);
            prefetch(1, 1);

            for (int kc = 0; kc < 8; kc++) {
                if (kc == 7) {
                    asm volatile("cp.async.wait_group 0;" ::: "memory");
                } else {
                    asm volatile("cp.async.wait_group 1;" ::: "memory");
                }
                __syncthreads();

                const uint32_t hsb = SB + R_HS + (kc & 1) * R_HBUF;
                const int ktg = kc * 64;
#pragma unroll
                for (int ks = 0; ks < 4; ks++) {
                    const int k0 = ks * 16;
                    uint32_t ah[2][4], al[2][4];
#pragma unroll
                    for (int mi = 0; mi < 2; mi++) {
                        uint32_t off = hsb +
                            (uint32_t)((warp_m * 32 + mi * 16 + a_r) * LDH +
                                       k0 + a_c) * 2;
                        ldsm4(off, ah[mi]);
                        ldsm4(off + R_HLO, al[mi]);
                    }
                    uint32_t bh[2][2], bl[2][2];
                    {
                        uint32_t off = SB + b_row_off +
                                       (uint32_t)(ktg + k0 + b_c) * 2;
                        uint32_t r4[4];
                        ldsm4(off, r4);
                        bh[0][0] = r4[0]; bh[0][1] = r4[1];
                        bh[1][0] = r4[2]; bh[1][1] = r4[3];
                        ldsm4(off + R_WS_LO, r4);
                        bl[0][0] = r4[0]; bl[0][1] = r4[1];
                        bl[1][0] = r4[2]; bl[1][1] = r4[3];
                    }
#pragma unroll
                    for (int mi = 0; mi < 2; mi++)
#pragma unroll
                        for (int ni = 0; ni < 2; ni++) {
                            mma16816(acc[mi][ni], ah[mi], bh[ni]);
                            mma16816(acc[mi][ni], ah[mi], bl[ni]);
                            mma16816(acc[mi][ni], al[mi], bh[ni]);
                        }
                }
                __syncthreads();
                if (kc < 6) prefetch(kc + 2, kc & 1);
            }
            // after kc==7: wait_group 0 done (gin tile included), sync passed
        } else {
            asm volatile("cp.async.wait_group 0;" ::: "memory");
            __syncthreads();
        }

        // ---- frags + gin(smem) -> Gs ----
#pragma unroll
        for (int mi = 0; mi < 2; mi++) {
            int r0 = warp_m * 32 + mi * 16 + (lane >> 2);
            int r1 = r0 + 8;
#pragma unroll
            for (int ni = 0; ni < 2; ni++) {
                int c = warp_n * 16 + ni * 8 + (lane & 3) * 2;  // == gate*8+jj
                float2 g0 = *(const float2*)(Gb + r0 * 36 + c);
                float2 g1 = *(const float2*)(Gb + r1 * 36 + c);
                Gs[r0 * 33 + c]     = acc[mi][ni][0] + g0.x;
                Gs[r0 * 33 + c + 1] = acc[mi][ni][1] + g0.y;
                Gs[r1 * 33 + c]     = acc[mi][ni][2] + g1.x;
                Gs[r1 * 33 + c + 1] = acc[mi][ni][3] + g1.y;
            }
        }
        __syncthreads();

        // ---- LSTM cell ----
        {
            int q0 = tid * 4;
            int bl = q0 >> 3;
            int jj0 = q0 & 7;
            float hhv[4];
#pragma unroll
            for (int s = 0; s < 4; s++) {
                int jj = jj0 + s;
                float gi = Gs[bl * 33 + jj];
                float gf = Gs[bl * 33 + 8 + jj];
                float gg = Gs[bl * 33 + 16 + jj];
                float go = Gs[bl * 33 + 24 + jj];
                float cprev = (t == 0) ? 0.f : Cs[bl * 8 + jj];
                float cc = sigmoidf_(gf) * cprev + sigmoidf_(gi) * tanhf(gg);
                hhv[s] = sigmoidf_(go) * tanhf(cc);
                Cs[bl * 8 + jj] = cc;
            }
            uint32_t h01, l01, h23, l23;
            split2(hhv[0], hhv[1], h01, l01);
            split2(hhv[2], hhv[3], h23, l23);
            // split hs output (consumed by out-GEMM)
            size_t ho = ((size_t)(bbase + bl) * TT + t) * HIDDEN + jbase + jj0;
            *(uint2*)&g_hs_s[0][ho] = make_uint2(h01, h23);
            *(uint2*)&g_hs_s[1][ho] = make_uint2(l01, l23);
            // packed h for next step
            int pc = (jbase + jj0) >> 1;
            g_hbuf_hi[t & 1][bbase + bl][pc]     = h01;
            g_hbuf_hi[t & 1][bbase + bl][pc + 1] = h23;
            g_hbuf_lo[t & 1][bbase + bl][pc]     = l01;
            g_hbuf_lo[t & 1][bbase + bl][pc + 1] = l23;
        }

        // ---- grid barrier (monotonic) ----
        if (t < TT - 1) {
            epoch++;
            __syncthreads();
            if (tid == 0) {
                __threadfence();
                unsigned arrived = atomicAdd(&g_count, 1u);
                if (arrived == epoch * NCTA - 1u) {
                    atomicExch(&g_epoch, epoch);
                } else {
                    volatile unsigned* ep = &g_epoch;
                    while (*ep < epoch) { __nanosleep(64); }
                }
                __threadfence();
            }
            __syncthreads();
        }
    }
}

// ==================== launch ====================
extern "C" void kernel_launch(void* const* d_in, const int* in_sizes, int n_in,
                              void* d_out, int out_size) {
    const float* images   = (const float*)d_in[0];   // [256, 2048]
    const float* captions = (const float*)d_in[1];   // [256, 128, 512]
    const float* W_fc     = (const float*)d_in[2];   // [256, 2048]
    const float* b_fc     = (const float*)d_in[3];   // [256]
    const float* W_att    = (const float*)d_in[4];   // [256, 768]
    const float* b_att    = (const float*)d_in[5];   // [256]
    const float* W_ih     = (const float*)d_in[6];   // [2048, 512]
    const float* b_ih     = (const float*)d_in[7];   // [2048]
    const float* W_hh     = (const float*)d_in[8];   // [2048, 512]
    const float* b_hh     = (const float*)d_in[9];   // [2048]
    const float* W_out    = (const float*)d_in[10];  // [1004, 512]
    const float* b_out    = (const float*)d_in[11];  // [1004]
    float* out = (float*)d_out;                      // [256, 128, 1004]

    static bool inited = false;
    static float *p_batt, *p_bih, *p_bsum, *p_gin;
    static uint16_t *im_h, *im_l, *wfc_h, *wfc_l, *wat_h, *wat_l,
                    *wih_h, *wih_l, *wo_h, *wo_l, *cap_h, *cap_l,
                    *fe_h, *fe_l, *cx_h, *cx_l, *hsh, *hsl;
    if (!inited) {
        inited = true;
        cudaGetSymbolAddress((void**)&p_batt, g_base_att);
        cudaGetSymbolAddress((void**)&p_bih, g_base_ih);
        cudaGetSymbolAddress((void**)&p_bsum, g_bsum);
        cudaGetSymbolAddress((void**)&p_gin, g_gin);
        uint16_t* t2;
        cudaGetSymbolAddress((void**)&t2, g_images_s); im_h = t2; im_l = t2 + BB * FC_IN;
        cudaGetSymbolAddress((void**)&t2, g_Wfc_s);   wfc_h = t2; wfc_l = t2 + EMBED * FC_IN;
        cudaGetSymbolAddress((void**)&t2, g_Watt_s);  wat_h = t2; wat_l = t2 + EMBED * (HIDDEN + EMBED);
        cudaGetSymbolAddress((void**)&t2, g_Wih_s);   wih_h = t2; wih_l = t2 + GATES * 2 * EMBED;
        cudaGetSymbolAddress((void**)&t2, g_Wout_s);  wo_h = t2;  wo_l = t2 + VOCAB * HIDDEN;
        cudaGetSymbolAddress((void**)&t2, g_capt_s);  cap_h = t2; cap_l = t2 + (size_t)BB * TT * HIDDEN;
        cudaGetSymbolAddress((void**)&t2, g_feats_s); fe_h = t2;  fe_l = t2 + BB * EMBED;
        cudaGetSymbolAddress((void**)&t2, g_ctx_s);   cx_h = t2;  cx_l = t2 + (size_t)BB * TT * EMBED;
        cudaGetSymbolAddress((void**)&t2, g_hs_s);    hsh = t2;   hsl = t2 + (size_t)BB * TT * HIDDEN;

        cudaFuncSetAttribute(lstm_persistent,
                             cudaFuncAttributeMaxDynamicSharedMemorySize, R_TOTAL);
        cudaFuncSetAttribute(gemm_bf<128, 128>,
                             cudaFuncAttributeMaxDynamicSharedMemorySize, 81920);
        cudaFuncSetAttribute(gemm_bf<64, 64>,
                             cudaFuncAttributeMaxDynamicSharedMemorySize, 40960);
    }

    auto split = [&](const float* X, uint16_t* Xh, uint16_t* Xl, size_t n) {
        int n4 = (int)(n / 4);
        split_kernel<<<(n4 + 255) / 256, 256>>>(X, Xh, Xl, n4);
    };
    auto tc = [&](const uint16_t* Ah, const uint16_t* Al, int lda,
                  const uint16_t* Bh, const uint16_t* Bl, int ldb,
                  const float* bias, const float* Cadd, int rowdiv,
                  float* C, uint16_t* Ch, uint16_t* Cl, int M, int N, int K) {
        dim3 grid((N + 127) / 128, M / 128);
        gemm_bf<128, 128><<<grid, 256, 81920>>>(Ah, Al, lda, Bh, Bl, ldb,
                                                bias, Cadd, rowdiv,
                                                C, Ch, Cl, M, N, K);
    };
    auto tcs = [&](const uint16_t* Ah, const uint16_t* Al, int lda,
                   const uint16_t* Bh, const uint16_t* Bl, int ldb,
                   const float* bias, const float* Cadd, int rowdiv,
                   float* C, uint16_t* Ch, uint16_t* Cl, int M, int N, int K) {
        dim3 grid((N + 63) / 64, M / 64);
        gemm_bf<64, 64><<<grid, 256, 40960>>>(Ah, Al, lda, Bh, Bl, ldb,
                                              bias, Cadd, rowdiv,
                                              C, Ch, Cl, M, N, K);
    };

    // init + convert inputs/weights to split bf16
    init_kernel<<<(GATES + 255) / 256, 256>>>(b_ih, b_hh, p_bsum);
    split(images, im_h, im_l, (size_t)BB * FC_IN);
    split(W_fc, wfc_h, wfc_l, (size_t)EMBED * FC_IN);
    split(W_att, wat_h, wat_l, (size_t)EMBED * (HIDDEN + EMBED));
    split(W_ih, wih_h, wih_l, (size_t)GATES * 2 * EMBED);
    split(W_out, wo_h, wo_l, (size_t)VOCAB * HIDDEN);
    split(captions, cap_h, cap_l, (size_t)BB * TT * HIDDEN);

    // feats(split) = images @ W_fc^T + b_fc            [256,256] K=2048
    tcs(im_h, im_l, FC_IN, wfc_h, wfc_l, FC_IN, b_fc, nullptr, 0,
        nullptr, fe_h, fe_l, BB, EMBED, FC_IN);

    // base_att = feats @ W_att[:, :256]^T + b_att      [256,256] K=256
    tcs(fe_h, fe_l, EMBED, wat_h, wat_l, HIDDEN + EMBED, b_att, nullptr, 0,
        p_batt, nullptr, nullptr, BB, EMBED, EMBED);

    // base_ih = feats @ W_ih[:, :256]^T + (b_ih+b_hh)  [256,2048] K=256
    tcs(fe_h, fe_l, EMBED, wih_h, wih_l, 2 * EMBED, p_bsum, nullptr, 0,
        p_bih, nullptr, nullptr, BB, GATES, EMBED);

    // ctx(split) = captions @ W_att[:, 256:]^T + base_att[b]   [32768,256] K=512
    tc(cap_h, cap_l, HIDDEN, wat_h + EMBED, wat_l + EMBED, HIDDEN + EMBED,
       nullptr, p_batt, TT, nullptr, cx_h, cx_l, BB * TT, EMBED, HIDDEN);

    // gin = ctx @ W_ih[:, 256:]^T + base_ih[b]         [32768,2048] K=256
    tc(cx_h, cx_l, EMBED, wih_h + EMBED, wih_l + EMBED, 2 * EMBED,
       nullptr, p_bih, TT, p_gin, nullptr, nullptr, BB * TT, GATES, EMBED);

    // full recurrence (writes split hs + hbuf)
    lstm_persistent<<<NCTA, 256, R_TOTAL>>>(W_hh, p_gin);

    // out = hs @ W_out^T + b_out                       [32768,1004] K=512
    tc(hsh, hsl, HIDDEN, wo_h, wo_l, HIDDEN, b_out, nullptr, 0,
       out, nullptr, nullptr, BB * TT, VOCAB, HIDDEN);
}